// round 1
// baseline (speedup 1.0000x reference)
#include <cuda_runtime.h>
#include <math.h>

// Problem dims
#define S  64
#define H  1024
#define V  512
#define WV 300
#define NE 512

// Recurrent kernel config
#define RB 32    // blocks (each owns 32 columns of ev)
#define RT 512   // threads per block: c = tid&31 (column), s = tid>>5 (row segment of 32)

// Output offsets (concatenated in reference return order)
#define OFF_ENTP 0
#define OFF_ACP  (S*NE)                  // 32768
#define OFF_ENT  (OFF_ACP + S*V)         // 65536
#define OFF_ALL  (OFF_ENT + S*H)         // 131072
#define OFF_ACT  (OFF_ALL + (size_t)S*NE*H)  // 33685504

// Scratch (device globals; no allocation allowed)
__device__ float g_ev[NE*H];
__device__ float g_Hbuf[S*H];
__device__ float g_HAT[S*H];
__device__ float g_AC[S*V];
__device__ float g_W2V[S*H];
__device__ float g_CHOICE[S*2];
__device__ float g_SCAL[S];
__device__ float g_LOGIT0[NE];
__device__ float g_PART[2*RB*NE];
__device__ unsigned g_barcnt;
__device__ volatile unsigned g_bargen;

// ---------------------------------------------------------------------------
// init: copy entity_vectors into working state, reset barrier
// ---------------------------------------------------------------------------
__global__ void k_init(const float* __restrict__ ev)
{
    int idx = blockIdx.x*blockDim.x + threadIdx.x;
    if (idx == 0) { g_barcnt = 0; g_bargen = 0; }
    int stride = gridDim.x*blockDim.x;
    for (int i = idx; i < NE*H; i += stride) g_ev[i] = ev[i];
}

// ---------------------------------------------------------------------------
// Tiled GEMM: C[64,N] = act( X[64,K] @ W[N,K]^T + b ), X optionally split
// (first K1 cols from X1 with row stride K1, rest from X2 with row stride K2s)
// act: 0 none, 1 relu, 2 sigmoid. Block computes a [64 x 32] tile.
// ---------------------------------------------------------------------------
__global__ void gemm64(const float* __restrict__ X1, int K1,
                       const float* __restrict__ X2, int K2s,
                       const float* __restrict__ W, const float* __restrict__ b,
                       float* __restrict__ C, int N, int K, int act)
{
    __shared__ float Xs[64][33];
    __shared__ float Ws[32][33];
    int tid = threadIdx.x;
    int tn = tid & 31, tg = tid >> 5;   // tg in 0..7
    int n0 = blockIdx.x * 32;

    float acc[8];
#pragma unroll
    for (int r = 0; r < 8; r++) acc[r] = 0.f;

    for (int kc = 0; kc < K; kc += 32) {
#pragma unroll
        for (int r = 0; r < 8; r++) {
            int e = tid + 256*r; int row = e >> 5, col = e & 31; int k = kc + col;
            Xs[row][col] = (k < K1) ? X1[row*K1 + k] : X2[row*K2s + (k - K1)];
        }
#pragma unroll
        for (int r = 0; r < 4; r++) {
            int e = tid + 256*r; int row = e >> 5, col = e & 31;
            Ws[row][col] = W[(size_t)(n0 + row)*K + kc + col];
        }
        __syncthreads();
#pragma unroll
        for (int kk = 0; kk < 32; kk++) {
            float w = Ws[tn][kk];
#pragma unroll
            for (int r = 0; r < 8; r++) acc[r] += Xs[tg*8 + r][kk] * w;
        }
        __syncthreads();
    }

    int n = n0 + tn;
    float bias = b[n];
#pragma unroll
    for (int r = 0; r < 8; r++) {
        float v = acc[r] + bias;
        if (act == 1)      v = fmaxf(v, 0.f);
        else if (act == 2) v = 1.f/(1.f + expf(-v));
        C[(size_t)(tg*8 + r)*N + n] = v;
    }
}

// ---------------------------------------------------------------------------
// Per-step small ops (one block per t, 128 threads):
//   ac_probs output, bar_ft (+step_act output), scal, choice softmax
// ---------------------------------------------------------------------------
__global__ void k_smalls(const float* __restrict__ emb,
                         const float* __restrict__ W3w, const float* __restrict__ W3b,
                         const float* __restrict__ W4w, const float* __restrict__ W4b,
                         float* __restrict__ out)
{
    int t = blockIdx.x;
    int tid = threadIdx.x;  // 128
    __shared__ float s_ac[V];
    __shared__ float s_bf[WV];
    __shared__ float s_red[128];
    __shared__ float s_cl[3];

    // load ac_prob, emit output, partial sum
    float psum = 0.f;
    for (int i = tid; i < V; i += 128) {
        float a = g_AC[t*V + i];
        s_ac[i] = a;
        out[OFF_ACP + t*V + i] = a;
        psum += a;
    }
    s_red[tid] = psum; __syncthreads();
    for (int off = 64; off; off >>= 1) { if (tid < off) s_red[tid] += s_red[tid+off]; __syncthreads(); }
    float acsum = s_red[0];
    __syncthreads();

    // bar_ft = (ac/sum) @ emb  -> step_act output
    for (int w = tid; w < WV; w += 128) {
        float acc = 0.f;
        for (int i = 0; i < V; i++) acc += s_ac[i]*emb[i*WV + w];
        float bf = acc / acsum;
        s_bf[w] = bf;
        out[OFF_ACT + t*WV + w] = bf;
    }
    __syncthreads();

    // scal = dot(bar_ft, W4w) + b
    float p = 0.f;
    for (int w = tid; w < WV; w += 128) p += s_bf[w]*W4w[w];
    s_red[tid] = p; __syncthreads();
    for (int off = 64; off; off >>= 1) { if (tid < off) s_red[tid] += s_red[tid+off]; __syncthreads(); }
    if (tid == 0) g_SCAL[t] = s_red[0] + W4b[0];

    // choice = softmax(hat @ W3w^T + b): warps 0..2 each do one dot
    int wid = tid >> 5, lane = tid & 31;
    if (wid < 3) {
        float a = 0.f;
        for (int k = lane; k < H; k += 32) a += g_HAT[t*H + k]*W3w[wid*H + k];
#pragma unroll
        for (int o = 16; o; o >>= 1) a += __shfl_xor_sync(0xffffffffu, a, o);
        if (lane == 0) s_cl[wid] = a + W3b[wid];
    }
    __syncthreads();
    if (tid == 0) {
        float m = fmaxf(s_cl[0], fmaxf(s_cl[1], s_cl[2]));
        float e0 = expf(s_cl[0]-m), e1 = expf(s_cl[1]-m), e2 = expf(s_cl[2]-m);
        float sm = e0 + e1 + e2;
        g_CHOICE[t*2+0] = e0/sm;
        g_CHOICE[t*2+1] = e1/sm;
    }
}

// ---------------------------------------------------------------------------
// logits for step 0: g_LOGIT0[i] = dot(ev0[i,:], w2v[0])   (one warp per row)
// ---------------------------------------------------------------------------
__global__ void k_logit0()
{
    int i = blockIdx.x*8 + (threadIdx.x >> 5);
    int lane = threadIdx.x & 31;
    const float* evr = g_ev + (size_t)i*H;
    float a = 0.f;
#pragma unroll
    for (int c = 0; c < H/32; c++) a += evr[lane + 32*c]*g_W2V[lane + 32*c];
#pragma unroll
    for (int o = 16; o; o >>= 1) a += __shfl_xor_sync(0xffffffffu, a, o);
    if (lane == 0) g_LOGIT0[i] = a;
}

// ---------------------------------------------------------------------------
// grid barrier (sense-reversing, RB blocks all resident)
// ---------------------------------------------------------------------------
__device__ __forceinline__ void gridbar()
{
    __syncthreads();
    __threadfence();
    if (threadIdx.x == 0) {
        unsigned gen = g_bargen;
        if (atomicAdd(&g_barcnt, 1u) == RB - 1) {
            g_barcnt = 0;
            __threadfence();
            g_bargen = gen + 1;
        } else {
            while (g_bargen == gen) { }
        }
    }
    __syncthreads();
}

// ---------------------------------------------------------------------------
// Persistent recurrent kernel: one grid barrier per step.
// Block blk owns columns j in [blk*32, blk*32+32). Per step:
//  stage1 (redundant per block): logits(t) = sum of per-block partials,
//          ent=sigmoid, attn, attn_sum; block0 writes ent_probs.
//  stage2: bar_et column reduce -> kt -> ev update + step_all snapshot,
//          fused next-step logit partials (warp-reduced, deterministic slots).
// ---------------------------------------------------------------------------
__global__ void __launch_bounds__(RT, 1) k_recurrent(float* __restrict__ out)
{
    int tid = threadIdx.x;
    int blk = blockIdx.x;
    int c = tid & 31;        // column within block (warp-contiguous -> coalesced)
    int s = tid >> 5;        // row segment 0..15 (32 rows each)
    int j = blk*32 + c;

    __shared__ float s_attn[NE];
    __shared__ float s_prev[NE];
    __shared__ float s_part[16][32];
    __shared__ float s_kt[32];
    __shared__ float s_red[16];
    __shared__ float s_sum;

    for (int i = tid; i < NE; i += RT) s_prev[i] = 0.f;
    __syncthreads();

    for (int t = 0; t < S; t++) {
        float c0   = g_CHOICE[t*2+0];
        float c1   = g_CHOICE[t*2+1];
        float scal = g_SCAL[t];

        // ---- stage 1: attn (RT == NE: one i per thread) ----
        float mysum;
        {
            int i = tid;
            float lg;
            if (t == 0) {
                lg = g_LOGIT0[i];
            } else {
                const float* pp = &g_PART[(t & 1)*RB*NE + i];
                float a = 0.f;
#pragma unroll
                for (int bb = 0; bb < RB; bb++) a += __ldcg(pp + bb*NE);
                lg = a;
            }
            float ent = 1.f/(1.f + expf(-lg));
            if (blk == 0) out[OFF_ENTP + t*NE + i] = ent;
            float at = c0*ent + c1*s_prev[i];
            s_prev[i] = ent;
            s_attn[i] = at;
            mysum = at;
        }
#pragma unroll
        for (int o = 16; o; o >>= 1) mysum += __shfl_xor_sync(0xffffffffu, mysum, o);
        if (c == 0) s_red[s] = mysum;
        __syncthreads();
        if (tid < 16) {
            float v = s_red[tid];
#pragma unroll
            for (int o = 8; o; o >>= 1) v += __shfl_xor_sync(0x0000ffffu, v, o);
            if (tid == 0) s_sum = v;
        }
        __syncthreads();
        float asum = s_sum;

        // ---- stage 2a: bar_et partial over this segment ----
        float* evc = g_ev + j;
        int i0 = s*32;
        float bacc = 0.f;
#pragma unroll 8
        for (int r = 0; r < 32; r++) {
            int i = i0 + r;
            bacc += s_attn[i]*evc[(size_t)i*H];
        }
        s_part[s][c] = bacc;
        __syncthreads();
        if (s == 0) {
            float bsum = 0.f;
#pragma unroll
            for (int q = 0; q < 16; q++) bsum += s_part[q][c];
            float bar = bsum / asum;
            out[OFF_ENT + t*H + j] = bar;
            s_kt[c] = fmaxf(scal*bar, 0.f);
        }
        __syncthreads();
        float kt = s_kt[c];

        // ---- stage 2b: ev update + snapshot + fused next-step logit partials
        float w2vn = (t < S-1) ? g_W2V[(t+1)*H + j] : 0.f;
        float* snap    = out + OFF_ALL + (size_t)t*NE*H + j;
        float* partout = &g_PART[((t+1) & 1)*RB*NE + blk*NE];
#pragma unroll 4
        for (int r = 0; r < 32; r++) {
            int i = i0 + r;
            float a   = s_attn[i];
            float old = evc[(size_t)i*H];
            float nv  = a*kt + (1.f - a)*old;
            evc[(size_t)i*H]    = nv;
            snap[(size_t)i*H]   = nv;
            float lp = nv*w2vn;
#pragma unroll
            for (int o = 16; o; o >>= 1) lp += __shfl_xor_sync(0xffffffffu, lp, o);
            if (c == 0) partout[i] = lp;   // deterministic per-block slot
        }
        gridbar();
    }
}

// ---------------------------------------------------------------------------
extern "C" void kernel_launch(void* const* d_in, const int* in_sizes, int n_in,
                              void* d_out, int out_size)
{
    (void)in_sizes; (void)n_in; (void)out_size;
    const float* vv  = (const float*)d_in[0];   // [1,64,1024]
    const float* ev  = (const float*)d_in[1];   // [512,1024]
    const float* A1w = (const float*)d_in[2];
    const float* A1b = (const float*)d_in[3];
    const float* A2w = (const float*)d_in[4];
    const float* A2b = (const float*)d_in[5];
    const float* emb = (const float*)d_in[6];
    const float* W1w = (const float*)d_in[7];
    const float* W1b = (const float*)d_in[8];
    const float* W2w = (const float*)d_in[9];
    const float* W2b = (const float*)d_in[10];
    const float* W3w = (const float*)d_in[11];
    const float* W3b = (const float*)d_in[12];
    const float* W4w = (const float*)d_in[13];
    const float* W4b = (const float*)d_in[14];
    float* out = (float*)d_out;

    float *pH, *pHAT, *pAC, *pW2V;
    cudaGetSymbolAddress((void**)&pH,   g_Hbuf);
    cudaGetSymbolAddress((void**)&pHAT, g_HAT);
    cudaGetSymbolAddress((void**)&pAC,  g_AC);
    cudaGetSymbolAddress((void**)&pW2V, g_W2V);

    k_init<<<256, 256>>>(ev);

    // Parallel prelude: everything that only depends on video_vectors
    gemm64<<<H/32, 256>>>(vv,   H, vv,  1, A1w, A1b, pH,   H, H,     1); // h = relu
    gemm64<<<H/32, 256>>>(vv,   H, vv,  1, W1w, W1b, pHAT, H, H,     1); // hat_ht = relu
    gemm64<<<V/32, 256>>>(pH,   H, pH,  1, A2w, A2b, pAC,  V, H,     2); // ac_prob = sigmoid
    gemm64<<<H/32, 256>>>(pHAT, H, pAC, V, W2w, W2b, pW2V, H, H + V, 0); // w2v (concat)

    k_smalls<<<S, 128>>>(emb, W3w, W3b, W4w, W4b, out);
    k_logit0<<<NE/8, 256>>>();

    // Sequential recurrence: one persistent cooperative-style kernel
    k_recurrent<<<RB, RT>>>(out);
}

// round 2
// speedup vs baseline: 2.0797x; 2.0797x over previous
#include <cuda_runtime.h>
#include <math.h>

// Problem dims
#define S  64
#define H  1024
#define V  512
#define WV 300
#define NE 512

// Recurrent kernel config
#define RB  64   // blocks; each owns RC columns of ev
#define RC  16   // columns per block (H / RB)
#define RT  512  // threads per block
#define SEG 32   // row segments (RT / RC)
#define RPT 16   // rows per thread (NE / SEG)

// Output offsets (concatenated in reference return order)
#define OFF_ENTP 0
#define OFF_ACP  (S*NE)
#define OFF_ENT  (OFF_ACP + S*V)
#define OFF_ALL  (OFF_ENT + S*H)
#define OFF_ACT  (OFF_ALL + (size_t)S*NE*H)

// Scratch (device globals; no allocation allowed)
__device__ float g_ev[NE*H];
__device__ float g_GP[8*64*H];       // split-K partials (max 8 x 64 x 1024)
__device__ float g_Hbuf[S*H];
__device__ float g_HAT[S*H];
__device__ float g_AC[S*V];
__device__ float g_W2V[S*H];
__device__ float g_CHOICE[S*2];
__device__ float g_SCAL[S];
__device__ float g_LOGIT0[NE];
__device__ float g_PART[2*RB*NE];
__device__ unsigned g_barcnt;
__device__ unsigned g_bargen;

// ---------------------------------------------------------------------------
__global__ void k_init(const float* __restrict__ ev)
{
    int idx = blockIdx.x*blockDim.x + threadIdx.x;
    if (idx == 0) { g_barcnt = 0; g_bargen = 0; }
    int stride = gridDim.x*blockDim.x;
    for (int i = idx; i < NE*H; i += stride) g_ev[i] = ev[i];
}

// ---------------------------------------------------------------------------
// Split-K GEMM partial: P[ky][64][N] += X[64, kslice] @ W[N, kslice]^T
// X split: first K1 cols from X1 (row stride K1), rest from X2 (row stride K2s)
// ---------------------------------------------------------------------------
__global__ void gemmSK(const float* __restrict__ X1, int K1,
                       const float* __restrict__ X2, int K2s,
                       const float* __restrict__ W,
                       float* __restrict__ P, int N, int K, int kslice)
{
    __shared__ float Xs[64][33];
    __shared__ float Ws[32][33];
    int tid = threadIdx.x;
    int tn = tid & 31, tg = tid >> 5;
    int n0 = blockIdx.x * 32;
    int kc0 = blockIdx.y * kslice;

    float acc[8];
#pragma unroll
    for (int r = 0; r < 8; r++) acc[r] = 0.f;

    for (int kc = kc0; kc < kc0 + kslice; kc += 32) {
#pragma unroll
        for (int r = 0; r < 8; r++) {
            int e = tid + 256*r; int row = e >> 5, col = e & 31; int k = kc + col;
            Xs[row][col] = (k < K1) ? X1[row*K1 + k] : X2[row*K2s + (k - K1)];
        }
#pragma unroll
        for (int r = 0; r < 4; r++) {
            int e = tid + 256*r; int row = e >> 5, col = e & 31;
            Ws[row][col] = W[(size_t)(n0 + row)*K + kc + col];
        }
        __syncthreads();
#pragma unroll
        for (int kk = 0; kk < 32; kk++) {
            float w = Ws[tn][kk];
#pragma unroll
            for (int r = 0; r < 8; r++) acc[r] += Xs[tg*8 + r][kk] * w;
        }
        __syncthreads();
    }

    float* Po = P + (size_t)blockIdx.y * 64 * N;
#pragma unroll
    for (int r = 0; r < 8; r++)
        Po[(size_t)(tg*8 + r)*N + n0 + tn] = acc[r];
}

// Reduce split-K partials, add bias, apply activation (0 none, 1 relu, 2 sigmoid)
__global__ void k_reduce(const float* __restrict__ P, const float* __restrict__ b,
                         float* __restrict__ C, int N, int KS, int act)
{
    int idx = blockIdx.x*256 + threadIdx.x;
    if (idx >= 64*N) return;
    float a = 0.f;
    for (int ks = 0; ks < KS; ks++) a += P[(size_t)ks*64*N + idx];
    a += b[idx % N];
    if (act == 1)      a = fmaxf(a, 0.f);
    else if (act == 2) a = 1.f/(1.f + expf(-a));
    C[idx] = a;
}

// ---------------------------------------------------------------------------
// Per-step small ops (one block per t, 128 threads)
// ---------------------------------------------------------------------------
__global__ void k_smalls(const float* __restrict__ emb,
                         const float* __restrict__ W3w, const float* __restrict__ W3b,
                         const float* __restrict__ W4w, const float* __restrict__ W4b,
                         float* __restrict__ out)
{
    int t = blockIdx.x;
    int tid = threadIdx.x;
    __shared__ float s_ac[V];
    __shared__ float s_bf[WV];
    __shared__ float s_red[128];
    __shared__ float s_cl[3];

    float psum = 0.f;
    for (int i = tid; i < V; i += 128) {
        float a = g_AC[t*V + i];
        s_ac[i] = a;
        out[OFF_ACP + t*V + i] = a;
        psum += a;
    }
    s_red[tid] = psum; __syncthreads();
    for (int off = 64; off; off >>= 1) { if (tid < off) s_red[tid] += s_red[tid+off]; __syncthreads(); }
    float acsum = s_red[0];
    __syncthreads();

    for (int w = tid; w < WV; w += 128) {
        float a0 = 0.f, a1 = 0.f, a2 = 0.f, a3 = 0.f;
        for (int i = 0; i < V; i += 4) {
            a0 += s_ac[i+0]*emb[(i+0)*WV + w];
            a1 += s_ac[i+1]*emb[(i+1)*WV + w];
            a2 += s_ac[i+2]*emb[(i+2)*WV + w];
            a3 += s_ac[i+3]*emb[(i+3)*WV + w];
        }
        float bf = ((a0+a1)+(a2+a3)) / acsum;
        s_bf[w] = bf;
        out[OFF_ACT + t*WV + w] = bf;
    }
    __syncthreads();

    float p = 0.f;
    for (int w = tid; w < WV; w += 128) p += s_bf[w]*W4w[w];
    s_red[tid] = p; __syncthreads();
    for (int off = 64; off; off >>= 1) { if (tid < off) s_red[tid] += s_red[tid+off]; __syncthreads(); }
    if (tid == 0) g_SCAL[t] = s_red[0] + W4b[0];

    int wid = tid >> 5, lane = tid & 31;
    if (wid < 3) {
        float a = 0.f;
        for (int k = lane; k < H; k += 32) a += g_HAT[t*H + k]*W3w[wid*H + k];
#pragma unroll
        for (int o = 16; o; o >>= 1) a += __shfl_xor_sync(0xffffffffu, a, o);
        if (lane == 0) s_cl[wid] = a + W3b[wid];
    }
    __syncthreads();
    if (tid == 0) {
        float m = fmaxf(s_cl[0], fmaxf(s_cl[1], s_cl[2]));
        float e0 = expf(s_cl[0]-m), e1 = expf(s_cl[1]-m), e2 = expf(s_cl[2]-m);
        float sm = e0 + e1 + e2;
        g_CHOICE[t*2+0] = e0/sm;
        g_CHOICE[t*2+1] = e1/sm;
    }
}

// ---------------------------------------------------------------------------
// logits for step 0 (one warp per row)
// ---------------------------------------------------------------------------
__global__ void k_logit0()
{
    int i = blockIdx.x*8 + (threadIdx.x >> 5);
    int lane = threadIdx.x & 31;
    const float* evr = g_ev + (size_t)i*H;
    float a = 0.f;
#pragma unroll
    for (int c = 0; c < H/32; c++) a += evr[lane + 32*c]*g_W2V[lane + 32*c];
#pragma unroll
    for (int o = 16; o; o >>= 1) a += __shfl_xor_sync(0xffffffffu, a, o);
    if (lane == 0) g_LOGIT0[i] = a;
}

// ---------------------------------------------------------------------------
// Release/acquire grid barrier, generation = target
// ---------------------------------------------------------------------------
__device__ __forceinline__ void gridbar(unsigned target)
{
    __syncthreads();
    if (threadIdx.x == 0) {
        unsigned prev;
        asm volatile("atom.add.release.gpu.global.u32 %0, [%1], 1;"
                     : "=r"(prev) : "l"(&g_barcnt) : "memory");
        if (prev == RB - 1) {
            g_barcnt = 0;
            asm volatile("st.release.gpu.global.u32 [%0], %1;"
                         :: "l"(&g_bargen), "r"(target) : "memory");
        } else {
            unsigned cur;
            do {
                asm volatile("ld.acquire.gpu.global.u32 %0, [%1];"
                             : "=r"(cur) : "l"(&g_bargen) : "memory");
            } while (cur < target);
        }
    }
    __syncthreads();
}

// ---------------------------------------------------------------------------
// Persistent recurrent kernel. Block blk owns columns [blk*RC, blk*RC+RC).
// ev lives in registers for the whole kernel (no one reads g_ev afterwards).
// One grid barrier per step; next-step logits accumulated as per-block partials.
// ---------------------------------------------------------------------------
__global__ void __launch_bounds__(RT, 1) k_recurrent(float* __restrict__ out)
{
    int tid = threadIdx.x;
    int blk = blockIdx.x;
    int c = tid & (RC-1);    // column within block
    int s = tid >> 4;        // row segment 0..31
    int j = blk*RC + c;
    int i0 = s*RPT;

    __shared__ float s_attn[NE];
    __shared__ float s_prev[NE];
    __shared__ float s_part[SEG][RC+1];
    __shared__ float s_kt[RC];
    __shared__ float s_red[16];
    __shared__ float s_sum;

    // cache this thread's ev slice in registers
    float evr[RPT];
    {
        const float* evc = g_ev + j;
#pragma unroll
        for (int r = 0; r < RPT; r++) evr[r] = evc[(size_t)(i0 + r)*H];
    }
    s_prev[tid] = 0.f;      // RT == NE
    __syncthreads();

    for (int t = 0; t < S; t++) {
        float c0   = g_CHOICE[t*2+0];
        float c1   = g_CHOICE[t*2+1];
        float scal = g_SCAL[t];

        // ---- stage 1: logits -> ent -> attn (one entity per thread) ----
        float at;
        {
            float lg;
            if (t == 0) {
                lg = g_LOGIT0[tid];
            } else {
                const float* pp = g_PART + (size_t)(t & 1)*RB*NE + tid;
                float a0 = 0.f, a1 = 0.f, a2 = 0.f, a3 = 0.f;
#pragma unroll
                for (int bb = 0; bb < RB; bb += 4) {
                    a0 += __ldcg(pp + (bb+0)*NE);
                    a1 += __ldcg(pp + (bb+1)*NE);
                    a2 += __ldcg(pp + (bb+2)*NE);
                    a3 += __ldcg(pp + (bb+3)*NE);
                }
                lg = (a0+a1)+(a2+a3);
            }
            float ent = 1.f/(1.f + expf(-lg));
            if (blk == 0) out[OFF_ENTP + t*NE + tid] = ent;
            at = c0*ent + c1*s_prev[tid];
            s_prev[tid] = ent;
            s_attn[tid] = at;
        }
        // attn sum over 512 threads
        float v = at;
#pragma unroll
        for (int o = 16; o; o >>= 1) v += __shfl_xor_sync(0xffffffffu, v, o);
        if ((tid & 31) == 0) s_red[tid >> 5] = v;
        __syncthreads();
        if (tid < 16) {
            float x = s_red[tid];
#pragma unroll
            for (int o = 8; o; o >>= 1) x += __shfl_xor_sync(0x0000ffffu, x, o);
            if (tid == 0) s_sum = x;
        }
        __syncthreads();
        float asum = s_sum;

        // ---- stage 2a: bar_et partial over this segment (ev from regs) ----
        float bacc = 0.f;
#pragma unroll
        for (int r = 0; r < RPT; r++) bacc += s_attn[i0 + r]*evr[r];
        s_part[s][c] = bacc;
        __syncthreads();
        if (tid < RC) {
            float bs = 0.f;
#pragma unroll
            for (int q = 0; q < SEG; q++) bs += s_part[q][tid];
            float bar = bs / asum;
            out[OFF_ENT + t*H + blk*RC + tid] = bar;
            s_kt[tid] = fmaxf(scal*bar, 0.f);
        }
        __syncthreads();
        float kt = s_kt[c];

        // ---- stage 2b: ev update + snapshot + fused next-step logit partials
        float w2vn = (t < S-1) ? g_W2V[(t+1)*H + j] : 0.f;
        float* snap    = out + OFF_ALL + (size_t)t*NE*H + j;
        float* partout = g_PART + (size_t)((t+1) & 1)*RB*NE + blk*NE;
#pragma unroll
        for (int r = 0; r < RPT; r++) {
            int i = i0 + r;
            float a  = s_attn[i];
            float nv = fmaf(a, kt - evr[r], evr[r]);   // a*kt + (1-a)*ev
            evr[r] = nv;
            __stcs(snap + (size_t)i*H, nv);
            float lp = nv*w2vn;
            lp += __shfl_xor_sync(0xffffffffu, lp, 8);
            lp += __shfl_xor_sync(0xffffffffu, lp, 4);
            lp += __shfl_xor_sync(0xffffffffu, lp, 2);
            lp += __shfl_xor_sync(0xffffffffu, lp, 1);
            if (c == 0) partout[i] = lp;
        }
        gridbar((unsigned)(t + 1));
    }
}

// ---------------------------------------------------------------------------
extern "C" void kernel_launch(void* const* d_in, const int* in_sizes, int n_in,
                              void* d_out, int out_size)
{
    (void)in_sizes; (void)n_in; (void)out_size;
    const float* vv  = (const float*)d_in[0];
    const float* ev  = (const float*)d_in[1];
    const float* A1w = (const float*)d_in[2];
    const float* A1b = (const float*)d_in[3];
    const float* A2w = (const float*)d_in[4];
    const float* A2b = (const float*)d_in[5];
    const float* emb = (const float*)d_in[6];
    const float* W1w = (const float*)d_in[7];
    const float* W1b = (const float*)d_in[8];
    const float* W2w = (const float*)d_in[9];
    const float* W2b = (const float*)d_in[10];
    const float* W3w = (const float*)d_in[11];
    const float* W3b = (const float*)d_in[12];
    const float* W4w = (const float*)d_in[13];
    const float* W4b = (const float*)d_in[14];
    float* out = (float*)d_out;

    float *pH, *pHAT, *pAC, *pW2V, *pGP;
    cudaGetSymbolAddress((void**)&pH,   g_Hbuf);
    cudaGetSymbolAddress((void**)&pHAT, g_HAT);
    cudaGetSymbolAddress((void**)&pAC,  g_AC);
    cudaGetSymbolAddress((void**)&pW2V, g_W2V);
    cudaGetSymbolAddress((void**)&pGP,  g_GP);

    k_init<<<256, 256>>>(ev);

    // h = relu(vv @ A1w^T + A1b)
    gemmSK<<<dim3(H/32, 8), 256>>>(vv, H, vv, 1, A1w, pGP, H, H, 128);
    k_reduce<<<(64*H + 255)/256, 256>>>(pGP, A1b, pH, H, 8, 1);
    // hat = relu(vv @ W1w^T + W1b)
    gemmSK<<<dim3(H/32, 8), 256>>>(vv, H, vv, 1, W1w, pGP, H, H, 128);
    k_reduce<<<(64*H + 255)/256, 256>>>(pGP, W1b, pHAT, H, 8, 1);
    // ac = sigmoid(h @ A2w^T + A2b)
    gemmSK<<<dim3(V/32, 8), 256>>>(pH, H, pH, 1, A2w, pGP, V, H, 128);
    k_reduce<<<(64*V + 255)/256, 256>>>(pGP, A2b, pAC, V, 8, 2);
    // w2v = concat(hat, ac) @ W2w^T + W2b
    gemmSK<<<dim3(H/32, 8), 256>>>(pHAT, H, pAC, V, W2w, pGP, H, H + V, 192);
    k_reduce<<<(64*H + 255)/256, 256>>>(pGP, W2b, pW2V, H, 8, 0);

    k_smalls<<<S, 128>>>(emb, W3w, W3b, W4w, W4b, out);
    k_logit0<<<NE/8, 256>>>();

    k_recurrent<<<RB, RT>>>(out);
}

// round 3
// speedup vs baseline: 2.0812x; 1.0007x over previous
#include <cuda_runtime.h>
#include <math.h>

// Problem dims
#define S  64
#define H  1024
#define V  512
#define WV 300
#define NE 512

// Recurrent kernel config
#define RB  64   // blocks; each owns RC columns of ev
#define RC  16
#define RT  512

// Output offsets (reference return order)
#define OFF_ENTP 0
#define OFF_ACP  (S*NE)
#define OFF_ENT  (OFF_ACP + S*V)
#define OFF_ALL  (OFF_ENT + S*H)
#define OFF_ACT  (OFF_ALL + (size_t)S*NE*H)

// Scratch (device globals; no allocation allowed)
__device__ __align__(16) float g_GP1[8*64*2048];  // h(0..1023)|hat(1024..2047) partials
__device__ __align__(16) float g_GP2[8*64*512];   // ac partials
__device__ __align__(16) float g_GP3[8*64*1024];  // w2v partials
__device__ __align__(16) float g_W2V[S*H];
__device__ float g_CHOICE[S*2];
__device__ float g_SCAL[S];
__device__ __align__(16) float g_PART[2*RB*NE];
__device__ unsigned g_barcnt;
__device__ unsigned g_bargen;

// ---------------------------------------------------------------------------
__global__ void k_init() { g_barcnt = 0; g_bargen = 0; }

// ---------------------------------------------------------------------------
// X loader with fused split-K reduction + activation of the PREVIOUS gemm.
// mode 0: dense Xd [64,K]
// mode 1: relu(bA + sum_ky GP1[ky][row][k])                 (h)
// mode 2: k<1024: relu(bA + sum GP1[ky][row][1024+k])       (hat)
//         k>=1024: sigmoid(bB + sum GP2[ky][row][k-1024])   (ac)
// ---------------------------------------------------------------------------
__device__ __forceinline__ float loadX(int mode, const float* __restrict__ Xd,
                                       const float* __restrict__ bA,
                                       const float* __restrict__ bB,
                                       int row, int k, int K)
{
    if (mode == 0) return Xd[row*K + k];
    if (mode == 1) {
        float a = bA[k];
#pragma unroll
        for (int ky = 0; ky < 8; ky++) a += g_GP1[ky*64*2048 + row*2048 + k];
        return fmaxf(a, 0.f);
    }
    if (k < 1024) {
        float a = bA[k];
#pragma unroll
        for (int ky = 0; ky < 8; ky++) a += g_GP1[ky*64*2048 + row*2048 + 1024 + k];
        return fmaxf(a, 0.f);
    } else {
        int kk = k - 1024;
        float a = bB[kk];
#pragma unroll
        for (int ky = 0; ky < 8; ky++) a += g_GP2[ky*64*512 + row*512 + kk];
        return 1.f/(1.f + expf(-a));
    }
}

// ---------------------------------------------------------------------------
// Split-K GEMM: OutP[ky][64][N] = X[64,kslice] @ W[N,kslice]^T
// 64x64 tile per block, 256 threads, 4x4 register blocking, float4 smem reads.
// W rows n<NB from Wa, else Wb (for fused h|hat weights).
// ---------------------------------------------------------------------------
__global__ void __launch_bounds__(256) gemmSK(
    int mode, const float* __restrict__ Xd,
    const float* __restrict__ bA, const float* __restrict__ bB,
    const float* __restrict__ Wa, const float* __restrict__ Wb, int NB,
    float* __restrict__ OutP, int N, int K, int kslice)
{
    __shared__ __align__(16) float XsT[32][68];
    __shared__ __align__(16) float WsT[32][68];
    int tid = threadIdx.x;
    int tx = tid & 15, ty = tid >> 4;
    int n0 = blockIdx.x * 64;
    int kc0 = blockIdx.y * kslice;

    float acc[4][4];
#pragma unroll
    for (int r = 0; r < 4; r++)
#pragma unroll
        for (int q = 0; q < 4; q++) acc[r][q] = 0.f;

    for (int kc = kc0; kc < kc0 + kslice; kc += 32) {
#pragma unroll
        for (int i = 0; i < 8; i++) {
            int e = tid + 256*i; int row = e >> 5; int kk = e & 31;
            XsT[kk][row] = loadX(mode, Xd, bA, bB, row, kc + kk, K);
        }
#pragma unroll
        for (int i = 0; i < 8; i++) {
            int e = tid + 256*i; int nr = e >> 5; int kk = e & 31;
            int n = n0 + nr;
            const float* Wp = (n < NB) ? (Wa + (size_t)n*K) : (Wb + (size_t)(n - NB)*K);
            WsT[kk][nr] = Wp[kc + kk];
        }
        __syncthreads();
#pragma unroll
        for (int kk = 0; kk < 32; kk++) {
            float4 xa = *(const float4*)&XsT[kk][ty*4];
            float4 wb = *(const float4*)&WsT[kk][tx*4];
            acc[0][0] += xa.x*wb.x; acc[0][1] += xa.x*wb.y; acc[0][2] += xa.x*wb.z; acc[0][3] += xa.x*wb.w;
            acc[1][0] += xa.y*wb.x; acc[1][1] += xa.y*wb.y; acc[1][2] += xa.y*wb.z; acc[1][3] += xa.y*wb.w;
            acc[2][0] += xa.z*wb.x; acc[2][1] += xa.z*wb.y; acc[2][2] += xa.z*wb.z; acc[2][3] += xa.z*wb.w;
            acc[3][0] += xa.w*wb.x; acc[3][1] += xa.w*wb.y; acc[3][2] += xa.w*wb.z; acc[3][3] += xa.w*wb.w;
        }
        __syncthreads();
    }
    float* Po = OutP + (size_t)blockIdx.y*64*N + n0;
#pragma unroll
    for (int r = 0; r < 4; r++) {
        float4 v = make_float4(acc[r][0], acc[r][1], acc[r][2], acc[r][3]);
        *(float4*)&Po[(size_t)(ty*4 + r)*N + tx*4] = v;
    }
}

// ---------------------------------------------------------------------------
// k_finish: blocks 0..63 = per-step smalls (t=blk); blocks 64..95 = w2v reduce.
// ---------------------------------------------------------------------------
__global__ void __launch_bounds__(256) k_finish(
    const float* __restrict__ emb,
    const float* __restrict__ A2b, const float* __restrict__ W1b,
    const float* __restrict__ W2b,
    const float* __restrict__ W3w, const float* __restrict__ W3b,
    const float* __restrict__ W4w, const float* __restrict__ W4b,
    float* __restrict__ out)
{
    int blk = blockIdx.x, tid = threadIdx.x;

    if (blk >= 64) {     // w2v = W2b + sum_ky GP3
        int b2 = blk - 64;
#pragma unroll
        for (int r = 0; r < 8; r++) {
            int idx = b2*2048 + tid + 256*r;       // idx = t*H + n
            int n = idx & (H-1);
            float a = W2b[n];
#pragma unroll
            for (int ky = 0; ky < 8; ky++) a += g_GP3[ky*64*1024 + idx];
            g_W2V[idx] = a;
        }
        return;
    }

    int t = blk;
    __shared__ float s_ac[V];
    __shared__ float s_bf[WV];
    __shared__ float s_red[256];
    __shared__ float s_cl[3];

    // ac = sigmoid(A2b + sum GP2); emit output; sum
    float psum = 0.f;
    for (int i = tid; i < V; i += 256) {
        float a = A2b[i];
#pragma unroll
        for (int ky = 0; ky < 8; ky++) a += g_GP2[ky*64*512 + t*512 + i];
        a = 1.f/(1.f + expf(-a));
        s_ac[i] = a;
        out[OFF_ACP + t*V + i] = a;
        psum += a;
    }
    s_red[tid] = psum; __syncthreads();
    for (int off = 128; off; off >>= 1) { if (tid < off) s_red[tid] += s_red[tid+off]; __syncthreads(); }
    float acsum = s_red[0];
    __syncthreads();

    // bar_ft = (ac/sum) @ emb
    for (int w = tid; w < WV; w += 256) {
        float a0 = 0.f, a1 = 0.f, a2 = 0.f, a3 = 0.f;
        for (int i = 0; i < V; i += 4) {
            a0 += s_ac[i+0]*emb[(i+0)*WV + w];
            a1 += s_ac[i+1]*emb[(i+1)*WV + w];
            a2 += s_ac[i+2]*emb[(i+2)*WV + w];
            a3 += s_ac[i+3]*emb[(i+3)*WV + w];
        }
        float bf = ((a0+a1)+(a2+a3)) / acsum;
        s_bf[w] = bf;
        out[OFF_ACT + t*WV + w] = bf;
    }
    __syncthreads();

    // scal
    float p = 0.f;
    for (int w = tid; w < WV; w += 256) p += s_bf[w]*W4w[w];
    s_red[tid] = p; __syncthreads();
    for (int off = 128; off; off >>= 1) { if (tid < off) s_red[tid] += s_red[tid+off]; __syncthreads(); }
    if (tid == 0) g_SCAL[t] = s_red[0] + W4b[0];

    // choice = softmax(hat @ W3w^T + b); hat reduced on the fly
    int wid = tid >> 5, lane = tid & 31;
    if (wid < 3) {
        float a = 0.f;
        for (int k = lane; k < H; k += 32) {
            float h = W1b[k];
#pragma unroll
            for (int ky = 0; ky < 8; ky++) h += g_GP1[ky*64*2048 + t*2048 + 1024 + k];
            h = fmaxf(h, 0.f);
            a += h*W3w[wid*H + k];
        }
#pragma unroll
        for (int o = 16; o; o >>= 1) a += __shfl_xor_sync(0xffffffffu, a, o);
        if (lane == 0) s_cl[wid] = a + W3b[wid];
    }
    __syncthreads();
    if (tid == 0) {
        float m = fmaxf(s_cl[0], fmaxf(s_cl[1], s_cl[2]));
        float e0 = expf(s_cl[0]-m), e1 = expf(s_cl[1]-m), e2 = expf(s_cl[2]-m);
        float sm = e0 + e1 + e2;
        g_CHOICE[t*2+0] = e0/sm;
        g_CHOICE[t*2+1] = e1/sm;
    }
}

// ---------------------------------------------------------------------------
// Release/acquire grid barrier (RB blocks all resident)
// ---------------------------------------------------------------------------
__device__ __forceinline__ void gridbar(unsigned target)
{
    __syncthreads();
    if (threadIdx.x == 0) {
        unsigned prev;
        asm volatile("atom.add.release.gpu.global.u32 %0, [%1], 1;"
                     : "=r"(prev) : "l"(&g_barcnt) : "memory");
        if (prev == RB - 1) {
            g_barcnt = 0;
            asm volatile("st.release.gpu.global.u32 [%0], %1;"
                         :: "l"(&g_bargen), "r"(target) : "memory");
        } else {
            unsigned cur;
            do {
                asm volatile("ld.acquire.gpu.global.u32 %0, [%1];"
                             : "=r"(cur) : "l"(&g_bargen) : "memory");
            } while (cur < target);
        }
    }
    __syncthreads();
}

// ---------------------------------------------------------------------------
// Persistent recurrent kernel. ev in registers; t=0 logits done in prologue;
// snapshot of step t-1 deferred into step t (overlaps gather; not drained by
// the barrier release of step t-1).
// ---------------------------------------------------------------------------
__global__ void __launch_bounds__(RT, 1) k_recurrent(const float* __restrict__ evin,
                                                     float* __restrict__ out)
{
    int tid = threadIdx.x;
    int blk = blockIdx.x;
    int c = tid & 15, s = tid >> 4;
    int j = blk*RC + c;
    int i0 = s*16;

    __shared__ float s_attn[NE];
    __shared__ float s_part[32][RC+1];
    __shared__ float s_kt[RC];
    __shared__ float s_red[16];
    __shared__ float s_sum;

    float evr[16];
#pragma unroll
    for (int r = 0; r < 16; r++) evr[r] = evin[(size_t)(i0 + r)*H + j];
    float prev = 0.f;

    // prologue: t=0 logit partials from register ev
    {
        float w = g_W2V[j];
        float* po = g_PART + blk*NE;
#pragma unroll
        for (int r = 0; r < 16; r++) {
            float lp = evr[r]*w;
            lp += __shfl_xor_sync(0xffffffffu, lp, 8);
            lp += __shfl_xor_sync(0xffffffffu, lp, 4);
            lp += __shfl_xor_sync(0xffffffffu, lp, 2);
            lp += __shfl_xor_sync(0xffffffffu, lp, 1);
            if (c == 0) po[i0 + r] = lp;
        }
    }
    gridbar(1);

    for (int t = 0; t < S; t++) {
        float c0   = g_CHOICE[t*2+0];
        float c1   = g_CHOICE[t*2+1];
        float scal = g_SCAL[t];

        // gather logit partials (issue first; L2 latency overlaps stores below)
        const float* pp = g_PART + (size_t)(t & 1)*RB*NE + tid;
        float a0 = 0.f, a1 = 0.f, a2 = 0.f, a3 = 0.f;
#pragma unroll
        for (int bb = 0; bb < RB; bb += 4) {
            a0 += __ldcg(pp + (bb+0)*NE);
            a1 += __ldcg(pp + (bb+1)*NE);
            a2 += __ldcg(pp + (bb+2)*NE);
            a3 += __ldcg(pp + (bb+3)*NE);
        }

        // deferred snapshot of step t-1 (evr holds ev_t)
        if (t > 0) {
            float* snap = out + OFF_ALL + (size_t)(t-1)*NE*H + j;
#pragma unroll
            for (int r = 0; r < 16; r++) __stcs(snap + (size_t)(i0 + r)*H, evr[r]);
        }

        float lg = (a0 + a1) + (a2 + a3);
        float ent = 1.f/(1.f + expf(-lg));
        if (blk == 0) out[OFF_ENTP + t*NE + tid] = ent;
        float at = fmaf(c0, ent, c1*prev);
        prev = ent;
        s_attn[tid] = at;

        float v = at;
#pragma unroll
        for (int o = 16; o; o >>= 1) v += __shfl_xor_sync(0xffffffffu, v, o);
        if ((tid & 31) == 0) s_red[tid >> 5] = v;
        __syncthreads();
        if (tid < 16) {
            float x = s_red[tid];
#pragma unroll
            for (int o = 8; o; o >>= 1) x += __shfl_xor_sync(0x0000ffffu, x, o);
            if (tid == 0) s_sum = x;
        }
        __syncthreads();
        float asum = s_sum;

        // bar_et partial (register ev)
        float bacc = 0.f;
#pragma unroll
        for (int r = 0; r < 16; r++) bacc += s_attn[i0 + r]*evr[r];
        s_part[s][c] = bacc;
        __syncthreads();
        if (tid < RC) {
            float bs = 0.f;
#pragma unroll
            for (int q = 0; q < 32; q++) bs += s_part[q][tid];
            float bar = bs / asum;
            out[OFF_ENT + t*H + blk*RC + tid] = bar;
            s_kt[tid] = fmaxf(scal*bar, 0.f);
        }
        __syncthreads();
        float kt = s_kt[c];

        if (t < S-1) {
            float w2vn = g_W2V[(t+1)*H + j];
            float* po = g_PART + (size_t)((t+1) & 1)*RB*NE + blk*NE;
#pragma unroll
            for (int r = 0; r < 16; r++) {
                float a  = s_attn[i0 + r];
                float nv = fmaf(a, kt - evr[r], evr[r]);
                evr[r] = nv;
                float lp = nv*w2vn;
                lp += __shfl_xor_sync(0xffffffffu, lp, 8);
                lp += __shfl_xor_sync(0xffffffffu, lp, 4);
                lp += __shfl_xor_sync(0xffffffffu, lp, 2);
                lp += __shfl_xor_sync(0xffffffffu, lp, 1);
                if (c == 0) po[i0 + r] = lp;
            }
            gridbar((unsigned)(t + 2));
        } else {
#pragma unroll
            for (int r = 0; r < 16; r++) {
                float a = s_attn[i0 + r];
                evr[r] = fmaf(a, kt - evr[r], evr[r]);
            }
            float* snap = out + OFF_ALL + (size_t)t*NE*H + j;
#pragma unroll
            for (int r = 0; r < 16; r++) __stcs(snap + (size_t)(i0 + r)*H, evr[r]);
        }
    }
}

// ---------------------------------------------------------------------------
extern "C" void kernel_launch(void* const* d_in, const int* in_sizes, int n_in,
                              void* d_out, int out_size)
{
    (void)in_sizes; (void)n_in; (void)out_size;
    const float* vv  = (const float*)d_in[0];
    const float* ev  = (const float*)d_in[1];
    const float* A1w = (const float*)d_in[2];
    const float* A1b = (const float*)d_in[3];
    const float* A2w = (const float*)d_in[4];
    const float* A2b = (const float*)d_in[5];
    const float* emb = (const float*)d_in[6];
    const float* W1w = (const float*)d_in[7];
    const float* W1b = (const float*)d_in[8];
    const float* W2w = (const float*)d_in[9];
    const float* W2b = (const float*)d_in[10];
    const float* W3w = (const float*)d_in[11];
    const float* W3b = (const float*)d_in[12];
    const float* W4w = (const float*)d_in[13];
    const float* W4b = (const float*)d_in[14];
    float* out = (float*)d_out;

    float *pGP1, *pGP2, *pGP3;
    cudaGetSymbolAddress((void**)&pGP1, g_GP1);
    cudaGetSymbolAddress((void**)&pGP2, g_GP2);
    cudaGetSymbolAddress((void**)&pGP3, g_GP3);

    // 0: barrier reset
    k_init<<<1, 1>>>();
    // 1: [h|hat] partials = vv @ [A1w|W1w]^T   (N=2048, K=1024)
    gemmSK<<<dim3(32, 8), 256>>>(0, vv, nullptr, nullptr, A1w, W1w, 1024,
                                 pGP1, 2048, 1024, 128);
    // 2: ac partials = relu(h) @ A2w^T         (N=512, K=1024)
    gemmSK<<<dim3(8, 8), 256>>>(1, nullptr, A1b, nullptr, A2w, A2w, 1<<30,
                                pGP2, 512, 1024, 128);
    // 3: w2v partials = [relu(hat)|sig(ac)] @ W2w^T  (N=1024, K=1536)
    gemmSK<<<dim3(16, 8), 256>>>(2, nullptr, W1b, A2b, W2w, W2w, 1<<30,
                                 pGP3, 1024, 1536, 192);
    // 4: smalls + w2v reduce
    k_finish<<<96, 256>>>(emb, A2b, W1b, W2b, W3w, W3b, W4w, W4b, out);
    // 5: recurrence (profiled by ncu -s 5 -c 1)
    k_recurrent<<<RB, RT>>>(ev, out);
}

// round 4
// speedup vs baseline: 2.2344x; 1.0736x over previous
#include <cuda_runtime.h>
#include <math.h>

// Problem dims
#define S  64
#define H  1024
#define V  512
#define WV 300
#define NE 512

// Recurrent kernel config
#define RB  64   // blocks; each owns RC columns of ev
#define RC  16
#define RT  512

// Output offsets (reference return order)
#define OFF_ENTP 0
#define OFF_ACP  (S*NE)
#define OFF_ENT  (OFF_ACP + S*V)
#define OFF_ALL  (OFF_ENT + S*H)
#define OFF_ACT  (OFF_ALL + (size_t)S*NE*H)

// Scratch (device globals; no allocation allowed)
__device__ __align__(16) float g_HH[64*2048];     // dense [relu(h) | relu(hat)]
__device__ __align__(16) float g_ACd[64*512];     // dense sigmoid(ac)
__device__ __align__(16) float g_GP3[8*64*1024];  // w2v split-K partials
__device__ __align__(16) float g_W2V[S*H];
__device__ float g_CHOICE[S*2];
__device__ float g_SCAL[S];
__device__ __align__(16) float g_PART[2*RB*NE];
__device__ unsigned g_barcnt;
__device__ unsigned g_bargen;

// ---------------------------------------------------------------------------
// Dense split-N GEMM: Out[64,N] = act( X[64,K] @ W[N,K]^T + b )
// 32x32 tile / block, 256 threads, 2x2 register blocking.
// W rows n<NB from Wa (bias bA), else Wb (bias bB). act: 1 relu, 2 sigmoid.
// Block (0,0) thread 0 also resets the grid barrier (safe: runs first).
// ---------------------------------------------------------------------------
__global__ void __launch_bounds__(256) gemm32(
    const float* __restrict__ X, int xstride,
    const float* __restrict__ Wa, const float* __restrict__ Wb, int NB,
    const float* __restrict__ bA, const float* __restrict__ bB,
    float* __restrict__ Out, int ostride, int K, int act)
{
    if (blockIdx.x == 0 && blockIdx.y == 0 && threadIdx.x == 0) {
        g_barcnt = 0; g_bargen = 0;
    }
    __shared__ __align__(8) float Xs[32][34];
    __shared__ __align__(8) float Ws[32][34];
    int tid = threadIdx.x;
    int tx = tid & 15, ty = tid >> 4;
    int n0 = blockIdx.x * 32;
    int m0 = blockIdx.y * 32;

    float a00 = 0.f, a01 = 0.f, a10 = 0.f, a11 = 0.f;

    for (int kc = 0; kc < K; kc += 32) {
#pragma unroll
        for (int i = 0; i < 4; i++) {
            int e = tid + 256*i; int row = e >> 5, kk = e & 31;
            Xs[kk][row] = X[(size_t)(m0 + row)*xstride + kc + kk];
        }
#pragma unroll
        for (int i = 0; i < 4; i++) {
            int e = tid + 256*i; int nr = e >> 5, kk = e & 31;
            int n = n0 + nr;
            const float* Wp = (n < NB) ? (Wa + (size_t)n*K) : (Wb + (size_t)(n - NB)*K);
            Ws[kk][nr] = Wp[kc + kk];
        }
        __syncthreads();
#pragma unroll
        for (int kk = 0; kk < 32; kk++) {
            float x0 = Xs[kk][ty*2], x1 = Xs[kk][ty*2+1];
            float w0 = Ws[kk][tx*2], w1 = Ws[kk][tx*2+1];
            a00 += x0*w0; a01 += x0*w1;
            a10 += x1*w0; a11 += x1*w1;
        }
        __syncthreads();
    }

    int n = n0 + tx*2;
    float b0 = (n   < NB) ? bA[n]   : bB[n   - NB];
    float b1 = (n+1 < NB) ? bA[n+1] : bB[n+1 - NB];
    float r[2][2] = {{a00 + b0, a01 + b1}, {a10 + b0, a11 + b1}};
#pragma unroll
    for (int q = 0; q < 2; q++)
#pragma unroll
        for (int p = 0; p < 2; p++) {
            float v = r[q][p];
            if (act == 1)      v = fmaxf(v, 0.f);
            else if (act == 2) v = 1.f/(1.f + expf(-v));
            Out[(size_t)(m0 + ty*2 + q)*ostride + n0 + tx*2 + p] = v;
        }
}

// ---------------------------------------------------------------------------
// Split-K GEMM for w2v partials: GP3[ky][64][1024] = X3[64,kslice] @ W2w^T
// X3 = [relu(hat) | sig(ac)] read densely from g_HH / g_ACd.
// 64x64 tiles, 4x4 register blocking.
// ---------------------------------------------------------------------------
__global__ void __launch_bounds__(256) gemm3(
    const float* __restrict__ W, float* __restrict__ OutP, int N, int K, int kslice)
{
    __shared__ __align__(16) float XsT[32][68];
    __shared__ __align__(16) float WsT[32][68];
    int tid = threadIdx.x;
    int tx = tid & 15, ty = tid >> 4;
    int n0 = blockIdx.x * 64;
    int kc0 = blockIdx.y * kslice;

    float acc[4][4];
#pragma unroll
    for (int r = 0; r < 4; r++)
#pragma unroll
        for (int q = 0; q < 4; q++) acc[r][q] = 0.f;

    for (int kc = kc0; kc < kc0 + kslice; kc += 32) {
#pragma unroll
        for (int i = 0; i < 8; i++) {
            int e = tid + 256*i; int row = e >> 5, kk = e & 31;
            int k = kc + kk;
            XsT[kk][row] = (k < 1024) ? g_HH[row*2048 + 1024 + k]
                                      : g_ACd[row*512 + (k - 1024)];
        }
#pragma unroll
        for (int i = 0; i < 8; i++) {
            int e = tid + 256*i; int nr = e >> 5, kk = e & 31;
            WsT[kk][nr] = W[(size_t)(n0 + nr)*K + kc + kk];
        }
        __syncthreads();
#pragma unroll
        for (int kk = 0; kk < 32; kk++) {
            float4 xa = *(const float4*)&XsT[kk][ty*4];
            float4 wb = *(const float4*)&WsT[kk][tx*4];
            acc[0][0] += xa.x*wb.x; acc[0][1] += xa.x*wb.y; acc[0][2] += xa.x*wb.z; acc[0][3] += xa.x*wb.w;
            acc[1][0] += xa.y*wb.x; acc[1][1] += xa.y*wb.y; acc[1][2] += xa.y*wb.z; acc[1][3] += xa.y*wb.w;
            acc[2][0] += xa.z*wb.x; acc[2][1] += xa.z*wb.y; acc[2][2] += xa.z*wb.z; acc[2][3] += xa.z*wb.w;
            acc[3][0] += xa.w*wb.x; acc[3][1] += xa.w*wb.y; acc[3][2] += xa.w*wb.z; acc[3][3] += xa.w*wb.w;
        }
        __syncthreads();
    }
    float* Po = OutP + (size_t)blockIdx.y*64*N + n0;
#pragma unroll
    for (int r = 0; r < 4; r++) {
        float4 v = make_float4(acc[r][0], acc[r][1], acc[r][2], acc[r][3]);
        *(float4*)&Po[(size_t)(ty*4 + r)*N + tx*4] = v;
    }
}

// ---------------------------------------------------------------------------
// Release/acquire grid barrier (RB blocks all resident)
// ---------------------------------------------------------------------------
__device__ __forceinline__ void gridbar(unsigned target)
{
    __syncthreads();
    if (threadIdx.x == 0) {
        unsigned prev;
        asm volatile("atom.add.release.gpu.global.u32 %0, [%1], 1;"
                     : "=r"(prev) : "l"(&g_barcnt) : "memory");
        if (prev == RB - 1) {
            g_barcnt = 0;
            asm volatile("st.release.gpu.global.u32 [%0], %1;"
                         :: "l"(&g_bargen), "r"(target) : "memory");
        } else {
            unsigned cur;
            do {
                asm volatile("ld.acquire.gpu.global.u32 %0, [%1];"
                             : "=r"(cur) : "l"(&g_bargen) : "memory");
            } while (cur < target);
        }
    }
    __syncthreads();
}

// ---------------------------------------------------------------------------
// Persistent recurrent kernel with fused "finish" prologue:
//   block t: smalls for step t (ac out, bar_ft/step_act out, scal, choice)
//            + w2v[t] reduce from GP3.   Then logit0 partials, then 64 steps.
// ---------------------------------------------------------------------------
__global__ void __launch_bounds__(RT, 1) k_recurrent(
    const float* __restrict__ evin,
    const float* __restrict__ emb,
    const float* __restrict__ W2b,
    const float* __restrict__ W3w, const float* __restrict__ W3b,
    const float* __restrict__ W4w, const float* __restrict__ W4b,
    float* __restrict__ out)
{
    int tid = threadIdx.x;
    int blk = blockIdx.x;
    int c = tid & 15, s = tid >> 4;
    int j = blk*RC + c;
    int i0 = s*16;
    int lane = tid & 31, wid = tid >> 5;

    __shared__ float s_attn[NE];
    __shared__ float s_part[32][RC+1];
    __shared__ float s_kt[RC];
    __shared__ float s_red[16];
    __shared__ float s_sum;
    __shared__ float s_ac[V];
    __shared__ float s_bf[WV];
    __shared__ float s_cl[3];

    // issue ev load early (DRAM latency overlaps the smalls below)
    float evr[16];
#pragma unroll
    for (int r = 0; r < 16; r++) evr[r] = evin[(size_t)(i0 + r)*H + j];

    // ================= prologue: smalls for step t = blk =================
    {
        int t = blk;
        // ac (dense, post-sigmoid): one element per thread
        float a = g_ACd[t*V + tid];
        s_ac[tid] = a;
        out[OFF_ACP + t*V + tid] = a;
        float v = a;
#pragma unroll
        for (int o = 16; o; o >>= 1) v += __shfl_xor_sync(0xffffffffu, v, o);
        if (lane == 0) s_red[wid] = v;
        __syncthreads();
        if (tid < 16) {
            float x = s_red[tid];
#pragma unroll
            for (int o = 8; o; o >>= 1) x += __shfl_xor_sync(0x0000ffffu, x, o);
            if (tid == 0) s_sum = x;
        }
        __syncthreads();
        float acsum = s_sum;

        // bar_ft = (ac/sum) @ emb  (threads 0..299, one output column each)
        if (tid < WV) {
            float a0 = 0.f, a1 = 0.f, a2 = 0.f, a3 = 0.f;
            for (int i = 0; i < V; i += 4) {
                a0 += s_ac[i+0]*emb[(i+0)*WV + tid];
                a1 += s_ac[i+1]*emb[(i+1)*WV + tid];
                a2 += s_ac[i+2]*emb[(i+2)*WV + tid];
                a3 += s_ac[i+3]*emb[(i+3)*WV + tid];
            }
            float bf = ((a0+a1)+(a2+a3)) / acsum;
            s_bf[tid] = bf;
            out[OFF_ACT + t*WV + tid] = bf;
        }
        __syncthreads();

        // scal = dot(bar_ft, W4w) + W4b
        float p = (tid < WV) ? s_bf[tid]*W4w[tid] : 0.f;
#pragma unroll
        for (int o = 16; o; o >>= 1) p += __shfl_xor_sync(0xffffffffu, p, o);
        if (lane == 0) s_red[wid] = p;
        __syncthreads();
        if (tid < 16) {
            float x = s_red[tid];
#pragma unroll
            for (int o = 8; o; o >>= 1) x += __shfl_xor_sync(0x0000ffffu, x, o);
            if (tid == 0) g_SCAL[t] = x + W4b[0];
        }

        // choice = softmax(hat @ W3w^T + W3b); hat dense in g_HH[:,1024:]
        if (wid < 3) {
            float a3v = 0.f;
            for (int k = lane; k < H; k += 32)
                a3v += g_HH[t*2048 + 1024 + k]*W3w[wid*H + k];
#pragma unroll
            for (int o = 16; o; o >>= 1) a3v += __shfl_xor_sync(0xffffffffu, a3v, o);
            if (lane == 0) s_cl[wid] = a3v + W3b[wid];
        }
        __syncthreads();
        if (tid == 0) {
            float m = fmaxf(s_cl[0], fmaxf(s_cl[1], s_cl[2]));
            float e0 = expf(s_cl[0]-m), e1 = expf(s_cl[1]-m), e2 = expf(s_cl[2]-m);
            float sm = e0 + e1 + e2;
            g_CHOICE[t*2+0] = e0/sm;
            g_CHOICE[t*2+1] = e1/sm;
        }

        // w2v[t] = W2b + sum_ky GP3[ky][t][:]
#pragma unroll
        for (int h2 = 0; h2 < 2; h2++) {
            int n = tid + 512*h2;
            float w = W2b[n];
#pragma unroll
            for (int ky = 0; ky < 8; ky++) w += g_GP3[ky*64*1024 + t*1024 + n];
            g_W2V[t*H + n] = w;
        }
    }
    gridbar(1);

    // logit0 partials from register ev
    {
        float w = g_W2V[j];
        float* po = g_PART + blk*NE;
#pragma unroll
        for (int r = 0; r < 16; r++) {
            float lp = evr[r]*w;
            lp += __shfl_xor_sync(0xffffffffu, lp, 8);
            lp += __shfl_xor_sync(0xffffffffu, lp, 4);
            lp += __shfl_xor_sync(0xffffffffu, lp, 2);
            lp += __shfl_xor_sync(0xffffffffu, lp, 1);
            if (c == 0) po[i0 + r] = lp;
        }
    }
    gridbar(2);

    // ========================= 64 sequential steps =========================
    float prev = 0.f;
    for (int t = 0; t < S; t++) {
        float c0   = g_CHOICE[t*2+0];
        float c1   = g_CHOICE[t*2+1];
        float scal = g_SCAL[t];

        // gather logit partials (L2 latency overlaps snapshot stores below)
        const float* pp = g_PART + (size_t)(t & 1)*RB*NE + tid;
        float a0 = 0.f, a1 = 0.f, a2 = 0.f, a3 = 0.f;
#pragma unroll
        for (int bb = 0; bb < RB; bb += 4) {
            a0 += __ldcg(pp + (bb+0)*NE);
            a1 += __ldcg(pp + (bb+1)*NE);
            a2 += __ldcg(pp + (bb+2)*NE);
            a3 += __ldcg(pp + (bb+3)*NE);
        }

        // deferred snapshot of step t-1 (evr holds ev_t)
        if (t > 0) {
            float* snap = out + OFF_ALL + (size_t)(t-1)*NE*H + j;
#pragma unroll
            for (int r = 0; r < 16; r++) __stcs(snap + (size_t)(i0 + r)*H, evr[r]);
        }

        float lg = (a0 + a1) + (a2 + a3);
        float ent = 1.f/(1.f + expf(-lg));
        if (blk == 0) out[OFF_ENTP + t*NE + tid] = ent;
        float at = fmaf(c0, ent, c1*prev);
        prev = ent;
        s_attn[tid] = at;

        float v = at;
#pragma unroll
        for (int o = 16; o; o >>= 1) v += __shfl_xor_sync(0xffffffffu, v, o);
        if (lane == 0) s_red[wid] = v;
        __syncthreads();
        if (tid < 16) {
            float x = s_red[tid];
#pragma unroll
            for (int o = 8; o; o >>= 1) x += __shfl_xor_sync(0x0000ffffu, x, o);
            if (tid == 0) s_sum = x;
        }
        __syncthreads();
        float asum = s_sum;

        // bar_et partial (register ev)
        float bacc = 0.f;
#pragma unroll
        for (int r = 0; r < 16; r++) bacc += s_attn[i0 + r]*evr[r];
        s_part[s][c] = bacc;
        __syncthreads();
        if (tid < RC) {
            float bs = 0.f;
#pragma unroll
            for (int q = 0; q < 32; q++) bs += s_part[q][tid];
            float bar = bs / asum;
            out[OFF_ENT + t*H + blk*RC + tid] = bar;
            s_kt[tid] = fmaxf(scal*bar, 0.f);
        }
        __syncthreads();
        float kt = s_kt[c];

        if (t < S-1) {
            float w2vn = g_W2V[(t+1)*H + j];
            float* po = g_PART + (size_t)((t+1) & 1)*RB*NE + blk*NE;
#pragma unroll
            for (int r = 0; r < 16; r++) {
                float a  = s_attn[i0 + r];
                float nv = fmaf(a, kt - evr[r], evr[r]);
                evr[r] = nv;
                float lp = nv*w2vn;
                lp += __shfl_xor_sync(0xffffffffu, lp, 8);
                lp += __shfl_xor_sync(0xffffffffu, lp, 4);
                lp += __shfl_xor_sync(0xffffffffu, lp, 2);
                lp += __shfl_xor_sync(0xffffffffu, lp, 1);
                if (c == 0) po[i0 + r] = lp;
            }
            gridbar((unsigned)(t + 3));
        } else {
#pragma unroll
            for (int r = 0; r < 16; r++) {
                float a = s_attn[i0 + r];
                evr[r] = fmaf(a, kt - evr[r], evr[r]);
            }
            float* snap = out + OFF_ALL + (size_t)t*NE*H + j;
#pragma unroll
            for (int r = 0; r < 16; r++) __stcs(snap + (size_t)(i0 + r)*H, evr[r]);
        }
    }
}

// ---------------------------------------------------------------------------
extern "C" void kernel_launch(void* const* d_in, const int* in_sizes, int n_in,
                              void* d_out, int out_size)
{
    (void)in_sizes; (void)n_in; (void)out_size;
    const float* vv  = (const float*)d_in[0];
    const float* ev  = (const float*)d_in[1];
    const float* A1w = (const float*)d_in[2];
    const float* A1b = (const float*)d_in[3];
    const float* A2w = (const float*)d_in[4];
    const float* A2b = (const float*)d_in[5];
    const float* emb = (const float*)d_in[6];
    const float* W1w = (const float*)d_in[7];
    const float* W1b = (const float*)d_in[8];
    const float* W2w = (const float*)d_in[9];
    const float* W2b = (const float*)d_in[10];
    const float* W3w = (const float*)d_in[11];
    const float* W3b = (const float*)d_in[12];
    const float* W4w = (const float*)d_in[13];
    const float* W4b = (const float*)d_in[14];
    float* out = (float*)d_out;

    float *pHH, *pAC, *pGP3;
    cudaGetSymbolAddress((void**)&pHH,  g_HH);
    cudaGetSymbolAddress((void**)&pAC,  g_ACd);
    cudaGetSymbolAddress((void**)&pGP3, g_GP3);

    // 0: [h|hat] = relu(vv @ [A1w|W1w]^T + [A1b|W1b])   N=2048 (also inits barrier)
    gemm32<<<dim3(64, 2), 256>>>(vv, H, A1w, W1w, 1024, A1b, W1b, pHH, 2048, H, 1);
    // 1: ac = sigmoid(h @ A2w^T + A2b)                  N=512
    gemm32<<<dim3(16, 2), 256>>>(pHH, 2048, A2w, A2w, 1<<30, A2b, A2b, pAC, 512, H, 2);
    // 2: w2v partials = [hat|ac] @ W2w^T                N=1024, K=1536, ky=8
    gemm3<<<dim3(16, 8), 256>>>(W2w, pGP3, 1024, 1536, 192);
    // 3: fused finish + recurrence (lands at profiled launch index 3)
    k_recurrent<<<RB, RT>>>(ev, emb, W2b, W3w, W3b, W4w, W4b, out);
}